// round 6
// baseline (speedup 1.0000x reference)
#include <cuda_runtime.h>
#include <cstddef>

// Shapes are fixed by the problem definition.
#define BB 32
#define FF 128
#define TT 8192

// Scratch (allocation-free rule: __device__ globals).
// At[b][i][r] : A-value column, transposed so main kernel stages contiguously.
// Dt[b][i][r] : At[b][i][min(r+1,127)] - At[b][i][r]  (row 127 -> 0, absorbs clamp)
__device__ float  g_At[BB * FF * FF];
__device__ float  g_Dt[BB * FF * FF];
// Per output-time-index j: {wy_j, bitcast(y0_j)}
__device__ float2 g_tab[TT];

// ---------------------------------------------------------------------------
// Kernel 1: build A (x-direction lerp) + forward diff along r.
// Thread index = b*16384 + i*128 + r  (matches At/Dt layout exactly).
// ---------------------------------------------------------------------------
__global__ void __launch_bounds__(256) k_build(const float* __restrict__ S) {
    int idx = blockIdx.x * 256 + threadIdx.x;
    if (idx >= BB * FF * FF) return;
    int r = idx & (FF - 1);
    int i = (idx >> 7) & (FF - 1);
    int b = idx >> 14;

    // x_pix = i/(F-1)*(T-1), clip, floor — faithful to reference fp32 math.
    float xpix = __fdiv_rn((float)i, (float)(FF - 1)) * (float)(TT - 1);
    xpix = fminf(fmaxf(xpix, 0.0f), (float)(TT - 1));
    float xf = floorf(xpix);
    int   x0 = (int)xf;
    int   x1 = min(x0 + 1, TT - 1);
    float wx = xpix - xf;

    int r1 = min(r + 1, FF - 1);
    const float* Sb = S + (size_t)b * FF * TT;
    float s00 = __ldg(Sb + (size_t)r  * TT + x0);
    float s01 = __ldg(Sb + (size_t)r  * TT + x1);
    float s10 = __ldg(Sb + (size_t)r1 * TT + x0);
    float s11 = __ldg(Sb + (size_t)r1 * TT + x1);

    float a  = fmaf(wx, s01 - s00, s00);   // (1-wx)*s00 + wx*s01
    float an = fmaf(wx, s11 - s10, s10);
    g_At[idx] = a;
    g_Dt[idx] = an - a;                    // r==127 -> r1==r -> exactly 0
}

// ---------------------------------------------------------------------------
// Kernel 2: per-j warp table (depends on source_pt / dest_pt device scalars).
// ---------------------------------------------------------------------------
__global__ void __launch_bounds__(256) k_tab(const int* __restrict__ src_p,
                                             const int* __restrict__ dst_p) {
    int j = blockIdx.x * 256 + threadIdx.x;
    if (j >= TT) return;
    float srcf = (float)(*src_p);
    float dstf = (float)(*dst_p);
    float lr = __fdiv_rn(dstf, srcf);                                    // dest/source
    float rr = __fdiv_rn((float)TT - dstf, (float)TT - srcf);            // (T-dest)/(T-source)

    float t   = (float)j;
    float ind = (t < dstf) ? __fdiv_rn(t, lr)
                           : (srcf + __fdiv_rn(t - dstf, rr));
    ind = fminf(fmaxf(ind, 0.0f), (float)(TT - 1));

    float ypix = __fdiv_rn(ind, (float)(TT - 1)) * (float)(FF - 1);
    ypix = fminf(fmaxf(ypix, 0.0f), (float)(FF - 1));
    float yf = floorf(ypix);
    int   y0 = (int)yf;
    float wy = ypix - yf;
    g_tab[j] = make_float2(wy, __int_as_float(y0));
}

// ---------------------------------------------------------------------------
// Kernel 3: main 128 MiB writer. 2 blocks per (b,i) row; each block stages the
// 128-float A/D columns in smem, then streams 4096 j's as float4 stores.
// Per warp per 128 outputs: 2 LDG.128 (table) + 8 broadcast LDS + 4 FFMA + 1 STG.128.
// ---------------------------------------------------------------------------
__global__ void __launch_bounds__(256) k_main(float* __restrict__ out) {
    __shared__ float sA[FF];
    __shared__ float sD[FF];

    int row  = blockIdx.x >> 1;      // b*128 + i, 0..4095
    int half = blockIdx.x & 1;       // which 4096-wide half of the time row
    int tid  = threadIdx.x;

    if (tid < FF)            sA[tid]       = g_At[row * FF + tid];
    else                     sD[tid - FF]  = g_Dt[row * FF + (tid - FF)];
    __syncthreads();

    const float4* tab4 = (const float4*)g_tab;              // 2 j-entries per float4
    float4* orow = (float4*)(out + (size_t)row * TT);       // 2048 groups per row

    int gbase = half * 1024;
#pragma unroll
    for (int k = 0; k < 4; k++) {
        int jg = gbase + k * 256 + tid;                     // group index, 0..2047
        float4 t01 = __ldg(&tab4[jg * 2]);                  // {wy0, y0, wy1, y1}
        float4 t23 = __ldg(&tab4[jg * 2 + 1]);              // {wy2, y2, wy3, y3}
        int o0 = __float_as_int(t01.y);
        int o1 = __float_as_int(t01.w);
        int o2 = __float_as_int(t23.y);
        int o3 = __float_as_int(t23.w);
        float4 o;
        o.x = fmaf(t01.x, sD[o0], sA[o0]);
        o.y = fmaf(t01.z, sD[o1], sA[o1]);
        o.z = fmaf(t23.x, sD[o2], sA[o2]);
        o.w = fmaf(t23.z, sD[o3], sA[o3]);
        orow[jg] = o;
    }
}

// ---------------------------------------------------------------------------
extern "C" void kernel_launch(void* const* d_in, const int* in_sizes, int n_in,
                              void* d_out, int out_size) {
    const float* S   = (const float*)d_in[0];
    const int*   src = (const int*)d_in[1];
    const int*   dst = (const int*)d_in[2];
    float*       out = (float*)d_out;
    (void)in_sizes; (void)n_in; (void)out_size;

    k_build<<<(BB * FF * FF + 255) / 256, 256>>>(S);
    k_tab<<<(TT + 255) / 256, 256>>>(src, dst);
    k_main<<<BB * FF * 2, 256>>>(out);
}